// round 3
// baseline (speedup 1.0000x reference)
#include <cuda_runtime.h>

// Swin-style shifted window attention, fused single kernel.
// x[8,96,256,256] f32, WIN=8, SHIFT=4, HEADS=3, dh=32, L=64 tokens/window.
// One CTA per window (8192 CTAs), 256 threads, ~132KB dynamic smem.
// Rolls folded into gather/scatter index: read & write both at (coord+4)&255.

#define C        96
#define DH       32
#define L        64
#define NWS      32               // 256/8 windows per side
#define NWINDOWS (8 * NWS * NWS)  // 8192
#define LNS      100              // padded row stride (floats) for 64xC buffers
#define ATTS     68               // padded row stride for 64x64 attention tile

#define SMEM_FLOATS (4 * L * LNS + L * ATTS + 32 * LNS)
#define SMEM_BYTES  (SMEM_FLOATS * 4)

__global__ __launch_bounds__(256, 1)
void swin_fused_kernel(const float* __restrict__ x,
                       const float* __restrict__ ln_g, const float* __restrict__ ln_b,
                       const float* __restrict__ w_qkv, const float* __restrict__ b_qkv,
                       const float* __restrict__ w_out, const float* __restrict__ b_out,
                       const float* __restrict__ w_proj, const float* __restrict__ b_proj,
                       float* __restrict__ out)
{
    extern __shared__ float sm[];
    float* bufA = sm;                 // [64][LNS]: xw -> y -> attn output O
    float* bufQ = bufA + L * LNS;     // [64][LNS]: q (scaled) -> out-gemm result
    float* bufK = bufQ + L * LNS;     // [64][LNS]: k -> final proj result (staging)
    float* bufV = bufK + L * LNS;     // [64][LNS]: v
    float* att  = bufV + L * LNS;     // [64][ATTS]
    float* wt   = att  + L * ATTS;    // [32][LNS]: staged weight tile

    const int tid = threadIdx.x;
    const int wb  = blockIdx.x;
    const int b   = wb / (NWS * NWS);
    const int wi  = wb % (NWS * NWS);
    const int h0  = (wi / NWS) * 8;
    const int w0  = (wi % NWS) * 8;

    const int cg = tid & 31;   // col within 32-col tile
    const int tg = tid >> 5;   // token group (8 tokens each)

    // ---------------- Phase 0: gather window (roll folded in) ----------------
    for (int li = tid; li < L * C; li += 256) {
        int t = li & 63, c = li >> 6;
        int hh = (h0 + (t >> 3) + 4) & 255;
        int wc = (w0 + (t & 7) + 4) & 255;
        bufA[t * LNS + c] = x[((b * C + c) * 256 + hh) * 256 + wc];
    }
    __syncthreads();

    // ---------------- Phase 1: LayerNorm over C (4 lanes per token) ----------
    {
        int t = tid >> 2, s = tid & 3;
        float sum = 0.f, sq = 0.f;
        for (int c = s; c < C; c += 4) {
            float v = bufA[t * LNS + c];
            sum += v; sq += v * v;
        }
        sum += __shfl_xor_sync(0xffffffffu, sum, 1);
        sum += __shfl_xor_sync(0xffffffffu, sum, 2);
        sq  += __shfl_xor_sync(0xffffffffu, sq, 1);
        sq  += __shfl_xor_sync(0xffffffffu, sq, 2);
        float mu  = sum * (1.0f / C);
        float var = sq * (1.0f / C) - mu * mu;
        float rs  = rsqrtf(var + 1e-5f);
        for (int c = s; c < C; c += 4) {
            float v = bufA[t * LNS + c];
            bufA[t * LNS + c] = (v - mu) * rs * ln_g[c] + ln_b[c];
        }
    }
    __syncthreads();

    // ---------------- Phase 2: QKV GEMM  y[64,96] @ w_qkv^T[96,288] ----------
    const float qscale = 0.17677669529663687f;  // 1/sqrt(32)
    for (int ct = 0; ct < 9; ct++) {
        for (int li = tid; li < 32 * C; li += 256) {
            int r = li / C, k = li - r * C;
            wt[r * LNS + k] = w_qkv[(ct * 32 + r) * C + k];
        }
        __syncthreads();
        int col = ct * 32 + cg;
        float bias = b_qkv[col];
        float acc[8];
        #pragma unroll
        for (int r = 0; r < 8; r++) acc[r] = bias;
        #pragma unroll 6
        for (int k = 0; k < C; k += 4) {
            float4 wv = *(const float4*)&wt[cg * LNS + k];
            #pragma unroll
            for (int r = 0; r < 8; r++) {
                float4 yv = *(const float4*)&bufA[(tg * 8 + r) * LNS + k];
                acc[r] += yv.x * wv.x + yv.y * wv.y + yv.z * wv.z + yv.w * wv.w;
            }
        }
        float* dst; int dc; float mul;
        if (col < 96)       { dst = bufQ; dc = col;       mul = qscale; }
        else if (col < 192) { dst = bufK; dc = col - 96;  mul = 1.f; }
        else                { dst = bufV; dc = col - 192; mul = 1.f; }
        #pragma unroll
        for (int r = 0; r < 8; r++)
            dst[(tg * 8 + r) * LNS + dc] = acc[r] * mul;
        __syncthreads();
    }

    // ---------------- Phase 3: attention per head -----------------------------
    for (int hd = 0; hd < 3; hd++) {
        const int ho = hd * DH;
        // S = q_h @ k_h^T   (16x16 thread grid, 4x4 micro-tile)
        {
            int txx = tid & 15, tyy = tid >> 4;
            int i0 = tyy * 4, j0 = txx * 4;
            float acc[4][4] = {};
            #pragma unroll
            for (int d = 0; d < DH; d += 4) {
                float4 qv[4], kv[4];
                #pragma unroll
                for (int r = 0; r < 4; r++)
                    qv[r] = *(const float4*)&bufQ[(i0 + r) * LNS + ho + d];
                #pragma unroll
                for (int cc = 0; cc < 4; cc++)
                    kv[cc] = *(const float4*)&bufK[(j0 + cc) * LNS + ho + d];
                #pragma unroll
                for (int r = 0; r < 4; r++)
                    #pragma unroll
                    for (int cc = 0; cc < 4; cc++)
                        acc[r][cc] += qv[r].x * kv[cc].x + qv[r].y * kv[cc].y +
                                      qv[r].z * kv[cc].z + qv[r].w * kv[cc].w;
            }
            #pragma unroll
            for (int r = 0; r < 4; r++)
                #pragma unroll
                for (int cc = 0; cc < 4; cc++)
                    att[(i0 + r) * ATTS + j0 + cc] = acc[r][cc];
        }
        __syncthreads();
        // softmax over rows (4 lanes per row)
        {
            int t = tid >> 2, s = tid & 3;
            float mx = -1e30f;
            for (int j = s; j < L; j += 4) mx = fmaxf(mx, att[t * ATTS + j]);
            mx = fmaxf(mx, __shfl_xor_sync(0xffffffffu, mx, 1));
            mx = fmaxf(mx, __shfl_xor_sync(0xffffffffu, mx, 2));
            float sum = 0.f;
            for (int j = s; j < L; j += 4) {
                float p = __expf(att[t * ATTS + j] - mx);
                att[t * ATTS + j] = p;
                sum += p;
            }
            sum += __shfl_xor_sync(0xffffffffu, sum, 1);
            sum += __shfl_xor_sync(0xffffffffu, sum, 2);
            float inv = 1.0f / sum;
            for (int j = s; j < L; j += 4) att[t * ATTS + j] *= inv;
        }
        __syncthreads();
        // O_h = P @ v_h  (32 d-lanes x 8 token groups, 8 rows per thread)
        {
            int d = tid & 31, tg2 = tid >> 5;
            float acc[8] = {};
            #pragma unroll 4
            for (int m = 0; m < L; m += 4) {
                float v0 = bufV[(m + 0) * LNS + ho + d];
                float v1 = bufV[(m + 1) * LNS + ho + d];
                float v2 = bufV[(m + 2) * LNS + ho + d];
                float v3 = bufV[(m + 3) * LNS + ho + d];
                #pragma unroll
                for (int r = 0; r < 8; r++) {
                    float4 p = *(const float4*)&att[(tg2 * 8 + r) * ATTS + m];
                    acc[r] += p.x * v0 + p.y * v1 + p.z * v2 + p.w * v3;
                }
            }
            #pragma unroll
            for (int r = 0; r < 8; r++)
                bufA[(tg2 * 8 + r) * LNS + ho + d] = acc[r];
        }
        __syncthreads();
    }

    // ---------------- Phase 4: out GEMM  O @ w_out^T + b_out -> bufQ ---------
    for (int ct = 0; ct < 3; ct++) {
        for (int li = tid; li < 32 * C; li += 256) {
            int r = li / C, k = li - r * C;
            wt[r * LNS + k] = w_out[(ct * 32 + r) * C + k];
        }
        __syncthreads();
        int col = ct * 32 + cg;
        float acc[8];
        float bias = b_out[col];
        #pragma unroll
        for (int r = 0; r < 8; r++) acc[r] = bias;
        #pragma unroll 6
        for (int k = 0; k < C; k += 4) {
            float4 wv = *(const float4*)&wt[cg * LNS + k];
            #pragma unroll
            for (int r = 0; r < 8; r++) {
                float4 yv = *(const float4*)&bufA[(tg * 8 + r) * LNS + k];
                acc[r] += yv.x * wv.x + yv.y * wv.y + yv.z * wv.z + yv.w * wv.w;
            }
        }
        #pragma unroll
        for (int r = 0; r < 8; r++)
            bufQ[(tg * 8 + r) * LNS + col] = acc[r];
        __syncthreads();
    }

    // ---------------- Phase 5: proj GEMM  -> bufK, then scatter --------------
    for (int ct = 0; ct < 3; ct++) {
        for (int li = tid; li < 32 * C; li += 256) {
            int r = li / C, k = li - r * C;
            wt[r * LNS + k] = w_proj[(ct * 32 + r) * C + k];
        }
        __syncthreads();
        int col = ct * 32 + cg;
        float acc[8];
        float bias = b_proj[col];
        #pragma unroll
        for (int r = 0; r < 8; r++) acc[r] = bias;
        #pragma unroll 6
        for (int k = 0; k < C; k += 4) {
            float4 wv = *(const float4*)&wt[cg * LNS + k];
            #pragma unroll
            for (int r = 0; r < 8; r++) {
                float4 yv = *(const float4*)&bufQ[(tg * 8 + r) * LNS + k];
                acc[r] += yv.x * wv.x + yv.y * wv.y + yv.z * wv.z + yv.w * wv.w;
            }
        }
        #pragma unroll
        for (int r = 0; r < 8; r++)
            bufK[(tg * 8 + r) * LNS + col] = acc[r];
        __syncthreads();
    }

    // scatter back (roll folded in; same index as gather)
    for (int li = tid; li < L * C; li += 256) {
        int t = li & 63, c = li >> 6;
        int hh = (h0 + (t >> 3) + 4) & 255;
        int wc = (w0 + (t & 7) + 4) & 255;
        out[((b * C + c) * 256 + hh) * 256 + wc] = bufK[t * LNS + c];
    }
}

extern "C" void kernel_launch(void* const* d_in, const int* in_sizes, int n_in,
                              void* d_out, int out_size) {
    const float* x      = (const float*)d_in[0];
    const float* ln_g   = (const float*)d_in[1];
    const float* ln_b   = (const float*)d_in[2];
    const float* w_qkv  = (const float*)d_in[3];
    const float* b_qkv  = (const float*)d_in[4];
    const float* w_out  = (const float*)d_in[5];
    const float* b_out  = (const float*)d_in[6];
    const float* w_proj = (const float*)d_in[7];
    const float* b_proj = (const float*)d_in[8];
    float* out = (float*)d_out;

    cudaFuncSetAttribute(swin_fused_kernel,
                         cudaFuncAttributeMaxDynamicSharedMemorySize, SMEM_BYTES);
    swin_fused_kernel<<<NWINDOWS, 256, SMEM_BYTES>>>(
        x, ln_g, ln_b, w_qkv, b_qkv, w_out, b_out, w_proj, b_proj, out);
}

// round 6
// speedup vs baseline: 3.7106x; 3.7106x over previous
#include <cuda_runtime.h>
#include <cstdint>

// Swin shifted-window attention, fused, GEMMs on tf32 mma.sync (tensor pipe).
// 1 window/CTA (L=64 tokens), 8192 CTAs, 256 threads, ~156KB dyn smem.
// Strides padded for conflict-free mma fragment LDS.

#define SA_Y   100   // XW / Y / O buffer stride
#define SA_Q   100
#define SA_K   100
#define SA_V   104
#define SA_P   68
#define SA_W   100

#define F_XW   0
#define F_Q    (F_XW + 64 * SA_Y)
#define F_K    (F_Q  + 64 * SA_Q)
#define F_V    (F_K  + 64 * SA_K)
#define F_P    (F_V  + 64 * SA_V)
#define F_W    (F_P  + 64 * SA_P)
#define SMEM_FLOATS (F_W + 96 * SA_W)
#define SMEM_BYTES  (SMEM_FLOATS * 4)

static __device__ __forceinline__ float tf32r(float x) {
    float y; asm("cvt.rna.tf32.f32 %0, %1;" : "=f"(y) : "f"(x)); return y;
}
static __device__ __forceinline__ void mma8(float* d, uint32_t a0, uint32_t a1,
                                            uint32_t a2, uint32_t a3,
                                            uint32_t b0, uint32_t b1) {
    asm volatile(
        "mma.sync.aligned.m16n8k8.row.col.f32.tf32.tf32.f32 "
        "{%0,%1,%2,%3}, {%4,%5,%6,%7}, {%8,%9}, {%0,%1,%2,%3};"
        : "+f"(d[0]), "+f"(d[1]), "+f"(d[2]), "+f"(d[3])
        : "r"(a0), "r"(a1), "r"(a2), "r"(a3), "r"(b0), "r"(b1));
}

// C[64,N] = A[64,K] @ B^T  with B stored [N,K] (weights layout).
// Warp grid: wm = wid&3 (16-row strip), wn = wid>>2. NSUB subtiles of 8 cols.
static __device__ __forceinline__ void wgemm_bt(
    const float* __restrict__ A, int SA,
    const float* __restrict__ B, int SB,
    float* __restrict__ Cd, int SD,
    int N, int K, int NSUB,
    const float* __restrict__ bias, float scale, bool rnd,
    int wm, int wn, int g, int t)
{
    const int TW = NSUB * 8;
    for (int nt = wn * TW; nt < N; nt += 2 * TW) {
        float acc[4][4];
        #pragma unroll
        for (int i = 0; i < 4; i++)
            #pragma unroll
            for (int j = 0; j < 4; j++) acc[i][j] = 0.f;
        #pragma unroll
        for (int k0 = 0; k0 < K; k0 += 8) {
            const float* Ar = A + k0 + t;
            uint32_t a0 = __float_as_uint(Ar[(wm * 16 + g) * SA]);
            uint32_t a1 = __float_as_uint(Ar[(wm * 16 + g + 8) * SA]);
            uint32_t a2 = __float_as_uint(Ar[(wm * 16 + g) * SA + 4]);
            uint32_t a3 = __float_as_uint(Ar[(wm * 16 + g + 8) * SA + 4]);
            #pragma unroll
            for (int ns = 0; ns < NSUB; ns++) {
                const float* Br = B + (nt + ns * 8 + g) * SB + k0 + t;
                mma8(acc[ns], a0, a1, a2, a3,
                     __float_as_uint(Br[0]), __float_as_uint(Br[4]));
            }
        }
        #pragma unroll
        for (int ns = 0; ns < NSUB; ns++) {
            int col = nt + ns * 8 + 2 * t;
            float bx = bias ? bias[col] : 0.f;
            float by = bias ? bias[col + 1] : 0.f;
            float v0 = (acc[ns][0] + bx) * scale;
            float v1 = (acc[ns][1] + by) * scale;
            float v2 = (acc[ns][2] + bx) * scale;
            float v3 = (acc[ns][3] + by) * scale;
            if (rnd) { v0 = tf32r(v0); v1 = tf32r(v1); v2 = tf32r(v2); v3 = tf32r(v3); }
            int r0 = wm * 16 + g;
            *(float2*)&Cd[r0 * SD + col]       = make_float2(v0, v1);
            *(float2*)&Cd[(r0 + 8) * SD + col] = make_float2(v2, v3);
        }
    }
}

// C[64,N] = A[64,K] @ B  with B stored [K,N] (P@V case).
static __device__ __forceinline__ void wgemm_bn(
    const float* __restrict__ A, int SA,
    const float* __restrict__ B, int SB,
    float* __restrict__ Cd, int SD,
    int N, int K, int NSUB,
    int wm, int wn, int g, int t)
{
    const int TW = NSUB * 8;
    for (int nt = wn * TW; nt < N; nt += 2 * TW) {
        float acc[4][4];
        #pragma unroll
        for (int i = 0; i < 4; i++)
            #pragma unroll
            for (int j = 0; j < 4; j++) acc[i][j] = 0.f;
        #pragma unroll
        for (int k0 = 0; k0 < K; k0 += 8) {
            const float* Ar = A + k0 + t;
            uint32_t a0 = __float_as_uint(Ar[(wm * 16 + g) * SA]);
            uint32_t a1 = __float_as_uint(Ar[(wm * 16 + g + 8) * SA]);
            uint32_t a2 = __float_as_uint(Ar[(wm * 16 + g) * SA + 4]);
            uint32_t a3 = __float_as_uint(Ar[(wm * 16 + g + 8) * SA + 4]);
            #pragma unroll
            for (int ns = 0; ns < NSUB; ns++) {
                const float* Br = B + (k0 + t) * SB + nt + ns * 8 + g;
                mma8(acc[ns], a0, a1, a2, a3,
                     __float_as_uint(Br[0]), __float_as_uint(Br[4 * SB]));
            }
        }
        #pragma unroll
        for (int ns = 0; ns < NSUB; ns++) {
            int col = nt + ns * 8 + 2 * t;
            int r0 = wm * 16 + g;
            *(float2*)&Cd[r0 * SD + col]       = make_float2(acc[ns][0], acc[ns][1]);
            *(float2*)&Cd[(r0 + 8) * SD + col] = make_float2(acc[ns][2], acc[ns][3]);
        }
    }
}

__global__ __launch_bounds__(256)
void swin_mma_kernel(const float* __restrict__ x,
                     const float* __restrict__ ln_g, const float* __restrict__ ln_b,
                     const float* __restrict__ w_qkv, const float* __restrict__ b_qkv,
                     const float* __restrict__ w_out, const float* __restrict__ b_out,
                     const float* __restrict__ w_proj, const float* __restrict__ b_proj,
                     float* __restrict__ out)
{
    extern __shared__ float sm[];
    float* XW  = sm + F_XW;   // x -> y -> O (attn output)
    float* Qb  = sm + F_Q;    // q -> out-gemm result
    float* Kb  = sm + F_K;    // k -> proj result (final staging)
    float* Vb  = sm + F_V;
    float* Pb  = sm + F_P;    // S -> P
    float* Wb  = sm + F_W;    // staged weight tile [<=96][SA_W]

    const int tid  = threadIdx.x;
    const int wid  = tid >> 5;
    const int lane = tid & 31;
    const int g    = lane >> 2;
    const int t4   = lane & 3;
    const int wm   = wid & 3;
    const int wn   = wid >> 2;

    const int wb = blockIdx.x;
    const int b  = wb >> 10;
    const int wy = (wb >> 5) & 31, wx = wb & 31;
    const int h0 = wy * 8, w0 = wx * 8;

    // ---- Phase 0: gather window (roll folded) ----
    for (int li = tid; li < 64 * 96; li += 256) {
        int tk = li & 63, c = li >> 6;
        int hh = (h0 + (tk >> 3) + 4) & 255;
        int wc = (w0 + (tk & 7) + 4) & 255;
        XW[tk * SA_Y + c] = x[((b * 96 + c) * 256 + hh) * 256 + wc];
    }
    __syncthreads();

    // ---- Phase 1: LayerNorm (4 lanes/token), write back tf32 ----
    {
        int tk = tid >> 2, s = tid & 3;
        float sum = 0.f, sq = 0.f;
        for (int c = s; c < 96; c += 4) {
            float v = XW[tk * SA_Y + c];
            sum += v; sq += v * v;
        }
        sum += __shfl_xor_sync(0xffffffffu, sum, 1);
        sum += __shfl_xor_sync(0xffffffffu, sum, 2);
        sq  += __shfl_xor_sync(0xffffffffu, sq, 1);
        sq  += __shfl_xor_sync(0xffffffffu, sq, 2);
        float mu = sum * (1.f / 96.f);
        float rs = rsqrtf(sq * (1.f / 96.f) - mu * mu + 1e-5f);
        for (int c = s; c < 96; c += 4) {
            float v = XW[tk * SA_Y + c];
            XW[tk * SA_Y + c] = tf32r((v - mu) * rs * ln_g[c] + ln_b[c]);
        }
    }
    __syncthreads();

    const float qscale = 0.17677669529663687f;  // 1/sqrt(32)

    // ---- Phase 2: QKV = Y @ w_qkv^T, three 96-col chunks ----
    #pragma unroll 1
    for (int ct = 0; ct < 3; ct++) {
        const float* src = w_qkv + ct * 96 * 96;
        for (int li = tid; li < 96 * 24; li += 256) {
            int row = li / 24, kc = (li % 24) * 4;
            float4 v = *(const float4*)(src + row * 96 + kc);
            v.x = tf32r(v.x); v.y = tf32r(v.y); v.z = tf32r(v.z); v.w = tf32r(v.w);
            *(float4*)&Wb[row * SA_W + kc] = v;
        }
        __syncthreads();
        if (ct == 0)
            wgemm_bt(XW, SA_Y, Wb, SA_W, Qb, SA_Q, 96, 96, 4,
                     b_qkv,       qscale, true, wm, wn, g, t4);
        else if (ct == 1)
            wgemm_bt(XW, SA_Y, Wb, SA_W, Kb, SA_K, 96, 96, 4,
                     b_qkv + 96,  1.f,    true, wm, wn, g, t4);
        else
            wgemm_bt(XW, SA_Y, Wb, SA_W, Vb, SA_V, 96, 96, 4,
                     b_qkv + 192, 1.f,    true, wm, wn, g, t4);
        __syncthreads();
    }

    // ---- Phase 3: attention per head ----
    #pragma unroll 1
    for (int hd = 0; hd < 3; hd++) {
        const int ho = hd * 32;
        // S = q_h @ k_h^T  ([64,64], K=32)
        wgemm_bt(Qb + ho, SA_Q, Kb + ho, SA_K, Pb, SA_P, 64, 32, 4,
                 (const float*)0, 1.f, false, wm, wn, g, t4);
        __syncthreads();
        // softmax rows (4 lanes/row), tf32-round P
        {
            int tk = tid >> 2, s = tid & 3;
            float mx = -1e30f;
            for (int j = s; j < 64; j += 4) mx = fmaxf(mx, Pb[tk * SA_P + j]);
            mx = fmaxf(mx, __shfl_xor_sync(0xffffffffu, mx, 1));
            mx = fmaxf(mx, __shfl_xor_sync(0xffffffffu, mx, 2));
            float sum = 0.f;
            for (int j = s; j < 64; j += 4) {
                float p = __expf(Pb[tk * SA_P + j] - mx);
                Pb[tk * SA_P + j] = p;
                sum += p;
            }
            sum += __shfl_xor_sync(0xffffffffu, sum, 1);
            sum += __shfl_xor_sync(0xffffffffu, sum, 2);
            float inv = 1.0f / sum;
            for (int j = s; j < 64; j += 4)
                Pb[tk * SA_P + j] = tf32r(Pb[tk * SA_P + j] * inv);
        }
        __syncthreads();
        // O_h = P @ V_h  ([64,32], K=64), write into XW cols ho..ho+31
        wgemm_bn(Pb, SA_P, Vb + ho, SA_V, XW + ho, SA_Y, 32, 64, 2,
                 wm, wn, g, t4);
        __syncthreads();
    }

    // ---- Phase 4: out GEMM  O @ w_out^T + b_out -> Qb (tf32) ----
    for (int li = tid; li < 96 * 24; li += 256) {
        int row = li / 24, kc = (li % 24) * 4;
        float4 v = *(const float4*)(w_out + row * 96 + kc);
        v.x = tf32r(v.x); v.y = tf32r(v.y); v.z = tf32r(v.z); v.w = tf32r(v.w);
        *(float4*)&Wb[row * SA_W + kc] = v;
    }
    __syncthreads();
    wgemm_bt(XW, SA_Y, Wb, SA_W, Qb, SA_Q, 96, 96, 4,
             b_out, 1.f, true, wm, wn, g, t4);
    __syncthreads();

    // ---- Phase 5: proj GEMM -> Kb (f32), then scatter ----
    for (int li = tid; li < 96 * 24; li += 256) {
        int row = li / 24, kc = (li % 24) * 4;
        float4 v = *(const float4*)(w_proj + row * 96 + kc);
        v.x = tf32r(v.x); v.y = tf32r(v.y); v.z = tf32r(v.z); v.w = tf32r(v.w);
        *(float4*)&Wb[row * SA_W + kc] = v;
    }
    __syncthreads();
    wgemm_bt(Qb, SA_Q, Wb, SA_W, Kb, SA_K, 96, 96, 4,
             b_proj, 1.f, false, wm, wn, g, t4);
    __syncthreads();

    for (int li = tid; li < 64 * 96; li += 256) {
        int tk = li & 63, c = li >> 6;
        int hh = (h0 + (tk >> 3) + 4) & 255;
        int wc = (w0 + (tk & 7) + 4) & 255;
        out[((b * 96 + c) * 256 + hh) * 256 + wc] = Kb[tk * SA_K + c];
    }
}

extern "C" void kernel_launch(void* const* d_in, const int* in_sizes, int n_in,
                              void* d_out, int out_size) {
    const float* x      = (const float*)d_in[0];
    const float* ln_g   = (const float*)d_in[1];
    const float* ln_b   = (const float*)d_in[2];
    const float* w_qkv  = (const float*)d_in[3];
    const float* b_qkv  = (const float*)d_in[4];
    const float* w_out  = (const float*)d_in[5];
    const float* b_out  = (const float*)d_in[6];
    const float* w_proj = (const float*)d_in[7];
    const float* b_proj = (const float*)d_in[8];
    float* out = (float*)d_out;

    cudaFuncSetAttribute(swin_mma_kernel,
                         cudaFuncAttributeMaxDynamicSharedMemorySize, SMEM_BYTES);
    swin_mma_kernel<<<8192, 256, SMEM_BYTES>>>(
        x, ln_g, ln_b, w_qkv, b_qkv, w_out, b_out, w_proj, b_proj, out);
}

// round 7
// speedup vs baseline: 5.7436x; 1.5479x over previous
#include <cuda_runtime.h>
#include <cstdint>

// Swin shifted-window attention, fused, tf32 mma.sync, 2 CTAs/SM.
// 1 window/CTA (L=64), 8192 CTAs, 256 threads, 93KB dyn smem.
// out+proj GEMMs folded into one via precombined Wc = w_proj@w_out (pre-kernel).
// Buffer reuse: XW: x->y->Q->final ; Kb: K->O(per-head cols) ; Vb: V ; PW: P <-> W-stage.

#define SA   100     // XW/Kb/W stride (g*100+t conflict-free)
#define SV   104     // Vb stride (t*104+g conflict-free for bn B-frags)
#define SP   68      // P stride

#define F_XW 0
#define F_K  6400
#define F_V  12800
#define F_PW 19456              // max(64*68, 32*100) = 4352
#define SMEM_FLOATS 23808
#define SMEM_BYTES  (SMEM_FLOATS * 4)

__device__ float g_wc[96 * 96];
__device__ float g_bc[96];

static __device__ __forceinline__ float tf32r(float x) {
    float y; asm("cvt.rna.tf32.f32 %0, %1;" : "=f"(y) : "f"(x)); return y;
}
static __device__ __forceinline__ void mma8(float* d, uint32_t a0, uint32_t a1,
                                            uint32_t a2, uint32_t a3,
                                            uint32_t b0, uint32_t b1) {
    asm volatile(
        "mma.sync.aligned.m16n8k8.row.col.f32.tf32.tf32.f32 "
        "{%0,%1,%2,%3}, {%4,%5,%6,%7}, {%8,%9}, {%0,%1,%2,%3};"
        : "+f"(d[0]), "+f"(d[1]), "+f"(d[2]), "+f"(d[3])
        : "r"(a0), "r"(a1), "r"(a2), "r"(a3), "r"(b0), "r"(b1));
}

// 16 x (NSUB*8) warp tile, B stored [N,K] (row n = output col). A,B pre-offset.
template<int K, int NSUB>
static __device__ __forceinline__ void mma_bt(const float* __restrict__ A, int SAs,
                                              const float* __restrict__ B, int SBs,
                                              float (&acc)[NSUB][4], int g, int t) {
    #pragma unroll
    for (int k0 = 0; k0 < K; k0 += 8) {
        const float* Ar = A + k0 + t;
        uint32_t a0 = __float_as_uint(Ar[g * SAs]);
        uint32_t a1 = __float_as_uint(Ar[(g + 8) * SAs]);
        uint32_t a2 = __float_as_uint(Ar[g * SAs + 4]);
        uint32_t a3 = __float_as_uint(Ar[(g + 8) * SAs + 4]);
        #pragma unroll
        for (int ns = 0; ns < NSUB; ns++) {
            const float* Br = B + (ns * 8 + g) * SBs + k0 + t;
            mma8(acc[ns], a0, a1, a2, a3,
                 __float_as_uint(Br[0]), __float_as_uint(Br[4]));
        }
    }
}
// 16 x (NSUB*8) warp tile, B stored [K,N]. A,B pre-offset.
template<int K, int NSUB>
static __device__ __forceinline__ void mma_bn(const float* __restrict__ A, int SAs,
                                              const float* __restrict__ B, int SBs,
                                              float (&acc)[NSUB][4], int g, int t) {
    #pragma unroll
    for (int k0 = 0; k0 < K; k0 += 8) {
        const float* Ar = A + k0 + t;
        uint32_t a0 = __float_as_uint(Ar[g * SAs]);
        uint32_t a1 = __float_as_uint(Ar[(g + 8) * SAs]);
        uint32_t a2 = __float_as_uint(Ar[g * SAs + 4]);
        uint32_t a3 = __float_as_uint(Ar[(g + 8) * SAs + 4]);
        #pragma unroll
        for (int ns = 0; ns < NSUB; ns++) {
            const float* Br = B + (k0 + t) * SBs + ns * 8 + g;
            mma8(acc[ns], a0, a1, a2, a3,
                 __float_as_uint(Br[0]), __float_as_uint(Br[4 * SBs]));
        }
    }
}

// Pre-kernel: Wc = w_proj @ w_out ; bc = w_proj @ b_out + b_proj  (fp32)
__global__ void combine_wb(const float* __restrict__ w_out, const float* __restrict__ b_out,
                           const float* __restrict__ w_proj, const float* __restrict__ b_proj) {
    int row = blockIdx.x, col = threadIdx.x;
    float s = 0.f;
    #pragma unroll 4
    for (int k = 0; k < 96; k++) s += w_proj[row * 96 + k] * w_out[k * 96 + col];
    g_wc[row * 96 + col] = s;
    if (col == 0) {
        float bs = b_proj[row];
        for (int k = 0; k < 96; k++) bs += w_proj[row * 96 + k] * b_out[k];
        g_bc[row] = bs;
    }
}

__global__ __launch_bounds__(256, 2)
void swin_mma2_kernel(const float* __restrict__ x,
                      const float* __restrict__ ln_g, const float* __restrict__ ln_b,
                      const float* __restrict__ w_qkv, const float* __restrict__ b_qkv,
                      float* __restrict__ out)
{
    extern __shared__ float sm[];
    float* XW = sm + F_XW;
    float* Kb = sm + F_K;
    float* Vb = sm + F_V;
    float* Pb = sm + F_PW;   // stride SP, attention phase
    float* Wb = sm + F_PW;   // stride SA, 32-row weight stage (time-shared)

    const int tid  = threadIdx.x;
    const int wid  = tid >> 5;
    const int lane = tid & 31;
    const int g    = lane >> 2;
    const int t4   = lane & 3;
    const int wm   = wid & 3;
    const int wn   = wid >> 2;

    const int wb = blockIdx.x;
    const int b  = wb >> 10;
    const int wy = (wb >> 5) & 31, wx = wb & 31;
    const int h0 = wy * 8, w0 = wx * 8;

    // ---- gather (roll folded) ----
    for (int li = tid; li < 64 * 96; li += 256) {
        int tk = li & 63, c = li >> 6;
        int hh = (h0 + (tk >> 3) + 4) & 255;
        int wc = (w0 + (tk & 7) + 4) & 255;
        XW[tk * SA + c] = x[((b * 96 + c) * 256 + hh) * 256 + wc];
    }
    __syncthreads();

    // ---- LayerNorm (4 lanes/token) ----
    {
        int tk = tid >> 2, s = tid & 3;
        float sum = 0.f, sq = 0.f;
        for (int c = s; c < 96; c += 4) {
            float v = XW[tk * SA + c];
            sum += v; sq += v * v;
        }
        sum += __shfl_xor_sync(0xffffffffu, sum, 1);
        sum += __shfl_xor_sync(0xffffffffu, sum, 2);
        sq  += __shfl_xor_sync(0xffffffffu, sq, 1);
        sq  += __shfl_xor_sync(0xffffffffu, sq, 2);
        float mu = sum * (1.f / 96.f);
        float rs = rsqrtf(sq * (1.f / 96.f) - mu * mu + 1e-5f);
        for (int c = s; c < 96; c += 4) {
            float v = XW[tk * SA + c];
            XW[tk * SA + c] = tf32r((v - mu) * rs * ln_g[c] + ln_b[c]);
        }
    }
    __syncthreads();

    const float qscale = 0.17677669529663687f;  // 1/sqrt(32)
    const float* Arow = XW + wm * 16 * SA;

    // ---- QKV: 9 chunks of 32 output features; Q held in registers ----
    float qacc[3][2][4];
    #pragma unroll
    for (int c = 0; c < 3; c++)
        #pragma unroll
        for (int i = 0; i < 2; i++)
            #pragma unroll
            for (int j = 0; j < 4; j++) qacc[c][i][j] = 0.f;

    #pragma unroll 1
    for (int ch = 0; ch < 9; ch++) {
        for (int li = tid; li < 32 * 24; li += 256) {
            int row = li / 24, kc = (li % 24) * 4;
            float4 v = *(const float4*)(w_qkv + (ch * 32 + row) * 96 + kc);
            v.x = tf32r(v.x); v.y = tf32r(v.y); v.z = tf32r(v.z); v.w = tf32r(v.w);
            *(float4*)&Wb[row * SA + kc] = v;
        }
        __syncthreads();
        if (ch < 3) {
            mma_bt<96, 2>(Arow, SA, Wb + wn * 16 * SA, SA, qacc[ch], g, t4);
        } else {
            float acc[2][4] = {};
            mma_bt<96, 2>(Arow, SA, Wb + wn * 16 * SA, SA, acc, g, t4);
            float* dst = (ch < 6) ? Kb : Vb;
            int SD     = (ch < 6) ? SA : SV;
            int cb     = ((ch < 6) ? (ch - 3) : (ch - 6)) * 32 + wn * 16;
            int gb     = ((ch < 6) ? 96 : 192) + cb;
            int r0 = wm * 16 + g;
            #pragma unroll
            for (int ns = 0; ns < 2; ns++) {
                int col = cb + ns * 8 + 2 * t4;
                float bx = b_qkv[gb + ns * 8 + 2 * t4];
                float by = b_qkv[gb + ns * 8 + 2 * t4 + 1];
                *(float2*)&dst[r0 * SD + col] =
                    make_float2(tf32r(acc[ns][0] + bx), tf32r(acc[ns][1] + by));
                *(float2*)&dst[(r0 + 8) * SD + col] =
                    make_float2(tf32r(acc[ns][2] + bx), tf32r(acc[ns][3] + by));
            }
        }
        __syncthreads();
    }
    // write Q (scaled) over y in XW
    {
        int r0 = wm * 16 + g;
        #pragma unroll
        for (int c = 0; c < 3; c++)
            #pragma unroll
            for (int ns = 0; ns < 2; ns++) {
                int col = c * 32 + wn * 16 + ns * 8 + 2 * t4;
                float bx = b_qkv[col], by = b_qkv[col + 1];
                *(float2*)&XW[r0 * SA + col] =
                    make_float2(tf32r((qacc[c][ns][0] + bx) * qscale),
                                tf32r((qacc[c][ns][1] + by) * qscale));
                *(float2*)&XW[(r0 + 8) * SA + col] =
                    make_float2(tf32r((qacc[c][ns][2] + bx) * qscale),
                                tf32r((qacc[c][ns][3] + by) * qscale));
            }
    }
    __syncthreads();

    // ---- attention: per head, S -> softmax -> O (O overwrites K_h cols in Kb) ----
    #pragma unroll 1
    for (int hd = 0; hd < 3; hd++) {
        const int ho = hd * 32;
        {
            float sacc[4][4] = {};
            mma_bt<32, 4>(XW + ho + wm * 16 * SA, SA,
                          Kb + ho + wn * 32 * SA, SA, sacc, g, t4);
            int r0 = wm * 16 + g;
            #pragma unroll
            for (int ns = 0; ns < 4; ns++) {
                int col = wn * 32 + ns * 8 + 2 * t4;
                *(float2*)&Pb[r0 * SP + col]       = make_float2(sacc[ns][0], sacc[ns][1]);
                *(float2*)&Pb[(r0 + 8) * SP + col] = make_float2(sacc[ns][2], sacc[ns][3]);
            }
        }
        __syncthreads();
        {
            int tk = tid >> 2, s = tid & 3;
            float mx = -1e30f;
            for (int j = s; j < 64; j += 4) mx = fmaxf(mx, Pb[tk * SP + j]);
            mx = fmaxf(mx, __shfl_xor_sync(0xffffffffu, mx, 1));
            mx = fmaxf(mx, __shfl_xor_sync(0xffffffffu, mx, 2));
            float sum = 0.f;
            for (int j = s; j < 64; j += 4) {
                float p = __expf(Pb[tk * SP + j] - mx);
                Pb[tk * SP + j] = p;
                sum += p;
            }
            sum += __shfl_xor_sync(0xffffffffu, sum, 1);
            sum += __shfl_xor_sync(0xffffffffu, sum, 2);
            float inv = 1.0f / sum;
            for (int j = s; j < 64; j += 4)
                Pb[tk * SP + j] = tf32r(Pb[tk * SP + j] * inv);
        }
        __syncthreads();
        {
            float oacc[2][4] = {};
            mma_bn<64, 2>(Pb + wm * 16 * SP, SP,
                          Vb + ho + wn * 16, SV, oacc, g, t4);
            int r0 = wm * 16 + g;
            #pragma unroll
            for (int ns = 0; ns < 2; ns++) {
                int col = ho + wn * 16 + ns * 8 + 2 * t4;
                *(float2*)&Kb[r0 * SA + col] =
                    make_float2(tf32r(oacc[ns][0]), tf32r(oacc[ns][1]));
                *(float2*)&Kb[(r0 + 8) * SA + col] =
                    make_float2(tf32r(oacc[ns][2]), tf32r(oacc[ns][3]));
            }
        }
        __syncthreads();
    }

    // ---- combined out∘proj GEMM: final = O @ Wc^T + bc  -> XW ----
    #pragma unroll 1
    for (int ch = 0; ch < 3; ch++) {
        for (int li = tid; li < 32 * 24; li += 256) {
            int row = li / 24, kc = (li % 24) * 4;
            float4 v = *(const float4*)(g_wc + (ch * 32 + row) * 96 + kc);
            v.x = tf32r(v.x); v.y = tf32r(v.y); v.z = tf32r(v.z); v.w = tf32r(v.w);
            *(float4*)&Wb[row * SA + kc] = v;
        }
        __syncthreads();
        float acc[2][4] = {};
        mma_bt<96, 2>(Kb + wm * 16 * SA, SA, Wb + wn * 16 * SA, SA, acc, g, t4);
        int r0 = wm * 16 + g;
        #pragma unroll
        for (int ns = 0; ns < 2; ns++) {
            int col = ch * 32 + wn * 16 + ns * 8 + 2 * t4;
            float bx = g_bc[col], by = g_bc[col + 1];
            *(float2*)&XW[r0 * SA + col] =
                make_float2(acc[ns][0] + bx, acc[ns][1] + by);
            *(float2*)&XW[(r0 + 8) * SA + col] =
                make_float2(acc[ns][2] + bx, acc[ns][3] + by);
        }
        __syncthreads();
    }

    // ---- scatter (roll folded) ----
    for (int li = tid; li < 64 * 96; li += 256) {
        int tk = li & 63, c = li >> 6;
        int hh = (h0 + (tk >> 3) + 4) & 255;
        int wc = (w0 + (tk & 7) + 4) & 255;
        out[((b * 96 + c) * 256 + hh) * 256 + wc] = XW[tk * SA + c];
    }
}

extern "C" void kernel_launch(void* const* d_in, const int* in_sizes, int n_in,
                              void* d_out, int out_size) {
    const float* x      = (const float*)d_in[0];
    const float* ln_g   = (const float*)d_in[1];
    const float* ln_b   = (const float*)d_in[2];
    const float* w_qkv  = (const float*)d_in[3];
    const float* b_qkv  = (const float*)d_in[4];
    const float* w_out  = (const float*)d_in[5];
    const float* b_out  = (const float*)d_in[6];
    const float* w_proj = (const float*)d_in[7];
    const float* b_proj = (const float*)d_in[8];
    float* out = (float*)d_out;

    combine_wb<<<96, 96>>>(w_out, b_out, w_proj, b_proj);
    cudaFuncSetAttribute(swin_mma2_kernel,
                         cudaFuncAttributeMaxDynamicSharedMemorySize, SMEM_BYTES);
    swin_mma2_kernel<<<8192, 256, SMEM_BYTES>>>(
        x, ln_g, ln_b, w_qkv, b_qkv, out);
}